// round 12
// baseline (speedup 1.0000x reference)
#include <cuda_runtime.h>
#include <cuda_fp16.h>
#include <stdint.h>

#define SPLITK 148
#define KCHUNK 32
#define LTOT   256
#define DDIM   128

// scratch (allocation-free rule: __device__ globals)
__device__ float g_p[200064];                       // exp(logits) per token
__device__ float g_part[SPLITK * LTOT * DDIM];      // split-K partial numerators
__device__ float g_zpart[SPLITK * LTOT];            // split-K partial denominators

// ---------------------------------------------------------------------------
// helpers
// ---------------------------------------------------------------------------
__device__ __forceinline__ void ldsm_x4(uint32_t* r, uint32_t addr) {
    asm volatile("ldmatrix.sync.aligned.m8n8.x4.shared.b16 {%0,%1,%2,%3}, [%4];"
        : "=r"(r[0]), "=r"(r[1]), "=r"(r[2]), "=r"(r[3]) : "r"(addr));
}
__device__ __forceinline__ void ldsm_x4_t(uint32_t* r, uint32_t addr) {
    asm volatile("ldmatrix.sync.aligned.m8n8.x4.trans.shared.b16 {%0,%1,%2,%3}, [%4];"
        : "=r"(r[0]), "=r"(r[1]), "=r"(r[2]), "=r"(r[3]) : "r"(addr));
}
__device__ __forceinline__ void mma_fp16(float* c, const uint32_t* a, uint32_t b0, uint32_t b1) {
    asm volatile("mma.sync.aligned.m16n8k16.row.col.f32.f16.f16.f32 "
        "{%0,%1,%2,%3}, {%4,%5,%6,%7}, {%8,%9}, {%0,%1,%2,%3};"
        : "+f"(c[0]), "+f"(c[1]), "+f"(c[2]), "+f"(c[3])
        : "r"(a[0]), "r"(a[1]), "r"(a[2]), "r"(a[3]), "r"(b0), "r"(b1));
}
__device__ __forceinline__ uint2 pack_half4(float x, float y, float z, float w) {
    __half2 lo = __floats2half2_rn(x, y);
    __half2 hi = __floats2half2_rn(z, w);
    uint2 v;
    v.x = *(uint32_t*)&lo;
    v.y = *(uint32_t*)&hi;
    return v;
}

// ---------------------------------------------------------------------------
// Kernel 1: p = exp(W2 . tanh(f @ W1 + b1) + b2), fp16 MMA.
// PERSISTENT + PIPELINED: 296 CTAs (2/SM), each loops over token tiles with
// double-buffered A smem and packed-fp16 register prefetch -> the next tile's
// LDGs are in flight during the current tile's MMA+epilogue. 1 sync/iter.
// ---------------------------------------------------------------------------
#define A1_STR 136
#define W1_STR 72
#define A1_HALVES (128*A1_STR)     // 17408 per buffer
#define SM1_BYTES ((2*A1_HALVES + 128*W1_STR) * 2)   // ~88 KB

__global__ __launch_bounds__(256, 2) void k1_logits(
    const float* __restrict__ feats, const float* __restrict__ W1,
    const float* __restrict__ b1, const float* __restrict__ W2,
    const float* __restrict__ b2, int B, int ntiles)
{
    extern __shared__ __half sm1[];
    __half* aS = sm1;                     // 2 x [128 tok][136]
    __half* wS = sm1 + 2*A1_HALVES;       // [128 k][72]

    int tid = threadIdx.x;
    int wid = tid >> 5, lane = tid & 31;
    int stride = gridDim.x;

    // stage W1 once per CTA
    #pragma unroll
    for (int i = 0; i < 8; i++) {
        int idx = tid + i*256;
        int row = idx >> 4, c4 = idx & 15;
        float4 v = ((const float4*)W1)[idx];
        *(uint2*)(wS + row*W1_STR + c4*4) = pack_half4(v.x, v.y, v.z, v.w);
    }

    uint32_t aS_s = (uint32_t)__cvta_generic_to_shared(aS);
    uint32_t wS_s = (uint32_t)__cvta_generic_to_shared(wS);

    // per-thread staging map: row = idx>>5 (token-in-tile), c4 = idx&31 (d/4)
    uint2 h4[16];

    // prefetch tile t0
    int t = blockIdx.x;
    {
        int tok0 = t * 128;
        #pragma unroll
        for (int i = 0; i < 16; i++) {
            int idx = tid + i*256;
            int tok = tok0 + (idx >> 5);
            float4 v = (tok < B) ? ((const float4*)(feats + (size_t)tok*DDIM))[idx & 31]
                                 : make_float4(0.f, 0.f, 0.f, 0.f);
            h4[i] = pack_half4(v.x, v.y, v.z, v.w);
        }
    }

    int buf = 0;
    for (; t < ntiles; t += stride) {
        int tok0 = t * 128;
        __half* aS_c = aS + buf * A1_HALVES;

        // stage tile t from regs
        #pragma unroll
        for (int i = 0; i < 16; i++) {
            int idx = tid + i*256;
            *(uint2*)(aS_c + (idx >> 5)*A1_STR + (idx & 31)*4) = h4[i];
        }
        // prefetch tile t+stride (in flight during MMA below)
        if (t + stride < ntiles) {
            int tok0n = (t + stride) * 128;
            #pragma unroll
            for (int i = 0; i < 16; i++) {
                int idx = tid + i*256;
                int tok = tok0n + (idx >> 5);
                float4 v = (tok < B) ? ((const float4*)(feats + (size_t)tok*DDIM))[idx & 31]
                                     : make_float4(0.f, 0.f, 0.f, 0.f);
                h4[i] = pack_half4(v.x, v.y, v.z, v.w);
            }
        }
        __syncthreads();   // aS_c staged; no warp still reads buf (see proof)

        // MMA: warp = 16 tok x 64 j over k=128
        uint32_t aS_b = aS_s + (uint32_t)(buf * A1_HALVES * 2);
        float acc[8][4];
        #pragma unroll
        for (int nt = 0; nt < 8; nt++)
            #pragma unroll
            for (int e = 0; e < 4; e++) acc[nt][e] = 0.f;

        #pragma unroll
        for (int ks = 0; ks < 8; ks++) {
            uint32_t a[4];
            ldsm_x4(a, aS_b + (uint32_t)(((wid*16 + (lane & 15)) * A1_STR
                              + ks*16 + ((lane >> 4) << 3)) * 2));
            #pragma unroll
            for (int np = 0; np < 4; np++) {
                uint32_t b[4];
                ldsm_x4_t(b, wS_s + (uint32_t)(((ks*16 + (lane & 15)) * W1_STR
                                  + np*16 + ((lane >> 4) << 3)) * 2));
                mma_fp16(acc[np*2],     a, b[0], b[1]);
                mma_fp16(acc[np*2 + 1], a, b[2], b[3]);
            }
        }

        // epilogue: +b1, tanh, dot W2, quad reduce, exp, store p
        float s0 = 0.f, s1 = 0.f;
        #pragma unroll
        for (int nt = 0; nt < 8; nt++) {
            int j0 = nt*8 + (lane & 3)*2;
            float b1a = __ldg(b1 + j0), b1b = __ldg(b1 + j0 + 1);
            float w2a = __ldg(W2 + j0), w2b = __ldg(W2 + j0 + 1);
            s0 += tanhf(acc[nt][0] + b1a) * w2a + tanhf(acc[nt][1] + b1b) * w2b;
            s1 += tanhf(acc[nt][2] + b1a) * w2a + tanhf(acc[nt][3] + b1b) * w2b;
        }
        #pragma unroll
        for (int m = 1; m <= 2; m <<= 1) {
            s0 += __shfl_xor_sync(0xffffffffu, s0, m);
            s1 += __shfl_xor_sync(0xffffffffu, s1, m);
        }
        if ((lane & 3) == 0) {
            float bb2 = __ldg(b2);
            int r = lane >> 2;
            int tok = tok0 + wid*16 + r;
            if (tok < B)     g_p[tok]     = expf(s0 + bb2);
            if (tok + 8 < B) g_p[tok + 8] = expf(s1 + bb2);
        }
        buf ^= 1;
    }
}

// ---------------------------------------------------------------------------
// Kernel 2: round-7 version verbatim (best measured). split-K fp16 MMA,
// KCHUNK=32, one 512-thread CTA per split covers all 256 l, register
// prefetch, double-buffered smem, 1 sync/chunk. warp = 32 l x 64 d.
// ---------------------------------------------------------------------------
#define MA_STR 40    // 32 k + 8 pad (halves)
#define G_STR  136   // 128 d + 8 pad (halves)
#define MA_HALVES (LTOT*MA_STR)   // 10240
#define G_HALVES  (KCHUNK*G_STR)  // 4352
#define SM2_BYTES ((2*MA_HALVES + 2*G_HALVES) * 2 + LTOT*8*4)

__global__ __launch_bounds__(512, 1) void k2_mma(
    const float* __restrict__ feats, const float* __restrict__ mask,
    int B, int chunksPerSplit)
{
    extern __shared__ char smraw[];
    __half* mA  = (__half*)smraw;                    // 2 x [256 l][40]
    __half* fS  = mA + 2*MA_HALVES;                  // 2 x [32 k][136]
    float*  zsm = (float*)(fS + 2*G_HALVES);         // [256][8]

    int tid  = threadIdx.x;
    int y    = blockIdx.x;
    int wid  = tid >> 5, lane = tid & 31;
    int wm   = wid & 7, wn = wid >> 3;

    float acc[2][8][4];
    #pragma unroll
    for (int mt = 0; mt < 2; mt++)
        #pragma unroll
        for (int nt = 0; nt < 8; nt++)
            #pragma unroll
            for (int e = 0; e < 4; e++) acc[mt][nt][e] = 0.f;
    float zacc[4] = {0.f, 0.f, 0.f, 0.f};

    uint32_t mA_s = (uint32_t)__cvta_generic_to_shared(mA);
    uint32_t fS_s = (uint32_t)__cvta_generic_to_shared(fS);

    int mrow = tid >> 3, mc4 = tid & 7;      // mask: l rows mrow+64i, k-col mc4*4

    float4 m4[4], f4[2], p4;
    int kb0 = y * chunksPerSplit * KCHUNK;

    // prologue: chunk 0 regs
    {
        int gk = kb0 + mc4*4;
        p4 = (gk < B) ? *((const float4*)(g_p + gk)) : make_float4(0.f,0.f,0.f,0.f);
        #pragma unroll
        for (int i = 0; i < 4; i++)
            m4[i] = (gk < B) ? *((const float4*)(mask + (size_t)(mrow + i*64)*B + gk))
                             : make_float4(0.f, 0.f, 0.f, 0.f);
        #pragma unroll
        for (int i = 0; i < 2; i++) {
            int idx = tid + i*512;
            int tok = kb0 + (idx >> 5);
            f4[i] = (tok < B) ? ((const float4*)(feats + (size_t)tok*DDIM))[idx & 31]
                              : make_float4(0.f, 0.f, 0.f, 0.f);
        }
    }

    for (int c = 0; c < chunksPerSplit; c++) {
        __half* mA_c = mA + (c & 1) * MA_HALVES;
        __half* fS_c = fS + (c & 1) * G_HALVES;

        // stage mp(c) = mask*p -> fp16; Z fused
        #pragma unroll
        for (int i = 0; i < 4; i++) {
            float4 v = m4[i];
            float mpx = v.x*p4.x, mpy = v.y*p4.y, mpz = v.z*p4.z, mpw = v.w*p4.w;
            zacc[i] += mpx + mpy + mpz + mpw;
            *(uint2*)(mA_c + (mrow + i*64)*MA_STR + mc4*4) = pack_half4(mpx, mpy, mpz, mpw);
        }
        // stage feats(c) fp32 regs -> fp16
        #pragma unroll
        for (int i = 0; i < 2; i++) {
            int idx = tid + i*512;
            *(uint2*)(fS_c + (idx >> 5)*G_STR + (idx & 31)*4)
                = pack_half4(f4[i].x, f4[i].y, f4[i].z, f4[i].w);
        }

        // prefetch chunk c+1 regs
        if (c + 1 < chunksPerSplit) {
            int kb2 = kb0 + (c + 1)*KCHUNK;
            int gk = kb2 + mc4*4;
            p4 = (gk < B) ? *((const float4*)(g_p + gk)) : make_float4(0.f,0.f,0.f,0.f);
            #pragma unroll
            for (int i = 0; i < 4; i++)
                m4[i] = (gk < B) ? *((const float4*)(mask + (size_t)(mrow + i*64)*B + gk))
                                 : make_float4(0.f, 0.f, 0.f, 0.f);
            #pragma unroll
            for (int i = 0; i < 2; i++) {
                int idx = tid + i*512;
                int tok = kb2 + (idx >> 5);
                f4[i] = (tok < B) ? ((const float4*)(feats + (size_t)tok*DDIM))[idx & 31]
                                  : make_float4(0.f, 0.f, 0.f, 0.f);
            }
        }
        __syncthreads();   // staged buffers visible; MMA(c-1) done

        // MMA over chunk c
        uint32_t mA_b = mA_s + (uint32_t)((c & 1) * MA_HALVES * 2);
        uint32_t fS_b = fS_s + (uint32_t)((c & 1) * G_HALVES * 2);
        #pragma unroll
        for (int ks = 0; ks < 2; ks++) {
            uint32_t a[2][4];
            #pragma unroll
            for (int mt = 0; mt < 2; mt++)
                ldsm_x4(a[mt], mA_b + (uint32_t)(((wm*32 + mt*16 + (lane & 15)) * MA_STR
                                 + ks*16 + ((lane >> 4) << 3)) * 2));
            #pragma unroll
            for (int np = 0; np < 4; np++) {
                uint32_t b[4];
                ldsm_x4_t(b, fS_b + (uint32_t)(((ks*16 + (lane & 15)) * G_STR
                                 + wn*64 + np*16 + ((lane >> 4) << 3)) * 2));
                #pragma unroll
                for (int mt = 0; mt < 2; mt++) {
                    mma_fp16(acc[mt][np*2],     a[mt], b[0], b[1]);
                    mma_fp16(acc[mt][np*2 + 1], a[mt], b[2], b[3]);
                }
            }
        }
    }

    // deterministic Z reduction
    __syncthreads();
    #pragma unroll
    for (int i = 0; i < 4; i++)
        zsm[(mrow + i*64)*8 + mc4] = zacc[i];
    __syncthreads();
    if (tid < LTOT) {
        float z = 0.f;
        #pragma unroll
        for (int j = 0; j < 8; j++) z += zsm[tid*8 + j];
        g_zpart[y*LTOT + tid] = z;
    }

    // write numerator partials
    #pragma unroll
    for (int mt = 0; mt < 2; mt++) {
        #pragma unroll
        for (int nt = 0; nt < 8; nt++) {
            int grow = wm*32 + mt*16 + (lane >> 2);
            int gcol = wn*64 + nt*8 + (lane & 3)*2;
            size_t b0 = ((size_t)y*LTOT + grow) * DDIM + gcol;
            size_t b1 = ((size_t)y*LTOT + grow + 8) * DDIM + gcol;
            *(float2*)(g_part + b0) = make_float2(acc[mt][nt][0], acc[mt][nt][1]);
            *(float2*)(g_part + b1) = make_float2(acc[mt][nt][2], acc[mt][nt][3]);
        }
    }
}

// ---------------------------------------------------------------------------
// Kernel 3: parallel reduce, FULL unroll -> all 37 loads in flight.
// ---------------------------------------------------------------------------
__global__ __launch_bounds__(512, 2) void k3_reduce(float* __restrict__ out)
{
    __shared__ float nsm[4][DDIM];
    __shared__ float zsm4[4];

    int l = blockIdx.x;
    int tid = threadIdx.x;
    int g = tid >> 7;
    int d = tid & 127;

    const float* pbase = g_part + ((size_t)(g*37)*LTOT + l) * DDIM + d;
    const float* zbase = g_zpart + (g*37)*LTOT + l;

    float n0 = 0.f, n1 = 0.f, z0 = 0.f, z1 = 0.f;
    #pragma unroll
    for (int yy = 0; yy < 37; yy += 2) {
        n0 += pbase[(size_t)yy * LTOT * DDIM];
        z0 += zbase[yy * LTOT];
    }
    #pragma unroll
    for (int yy = 1; yy < 37; yy += 2) {
        n1 += pbase[(size_t)yy * LTOT * DDIM];
        z1 += zbase[yy * LTOT];
    }
    nsm[g][d] = n0 + n1;
    if (d == 0) zsm4[g] = z0 + z1;
    __syncthreads();

    if (g == 0) {
        float n = nsm[0][d] + nsm[1][d] + nsm[2][d] + nsm[3][d];
        float zz = zsm4[0] + zsm4[1] + zsm4[2] + zsm4[3];
        out[l*DDIM + d] = (zz > 0.f) ? n / zz : 0.f;
    }
}

// ---------------------------------------------------------------------------
extern "C" void kernel_launch(void* const* d_in, const int* in_sizes, int n_in,
                              void* d_out, int out_size)
{
    const float* feats = (const float*)d_in[0];
    const float* mask  = (const float*)d_in[1];
    const float* W1    = (const float*)d_in[2];
    const float* b1    = (const float*)d_in[3];
    const float* W2    = (const float*)d_in[4];
    const float* b2    = (const float*)d_in[5];
    float* out = (float*)d_out;

    int B = in_sizes[0] / DDIM;           // 200000
    int totalChunks = (B + KCHUNK - 1) / KCHUNK;
    int cps = (totalChunks + SPLITK - 1) / SPLITK;
    int ntiles = (B + 127) / 128;

    cudaFuncSetAttribute(k1_logits, cudaFuncAttributeMaxDynamicSharedMemorySize, SM1_BYTES);
    cudaFuncSetAttribute(k2_mma,    cudaFuncAttributeMaxDynamicSharedMemorySize, SM2_BYTES);

    k1_logits<<<296, 256, SM1_BYTES>>>(feats, W1, b1, W2, b2, B, ntiles);

    k2_mma<<<SPLITK, 512, SM2_BYTES>>>(feats, mask, B, cps);

    k3_reduce<<<LTOT, 512>>>(out);
}

// round 13
// speedup vs baseline: 1.0664x; 1.0664x over previous
#include <cuda_runtime.h>
#include <cuda_fp16.h>
#include <stdint.h>

#define SPLITK 148
#define KCHUNK 32
#define LTOT   256
#define DDIM   128

// scratch (allocation-free rule: __device__ globals)
__device__ float g_p[200064];                       // exp(logits) per token
__device__ float g_part[SPLITK * LTOT * DDIM];      // split-K partial numerators
__device__ float g_zpart[SPLITK * LTOT];            // split-K partial denominators

// ---------------------------------------------------------------------------
// helpers
// ---------------------------------------------------------------------------
__device__ __forceinline__ void ldsm_x4(uint32_t* r, uint32_t addr) {
    asm volatile("ldmatrix.sync.aligned.m8n8.x4.shared.b16 {%0,%1,%2,%3}, [%4];"
        : "=r"(r[0]), "=r"(r[1]), "=r"(r[2]), "=r"(r[3]) : "r"(addr));
}
__device__ __forceinline__ void ldsm_x4_t(uint32_t* r, uint32_t addr) {
    asm volatile("ldmatrix.sync.aligned.m8n8.x4.trans.shared.b16 {%0,%1,%2,%3}, [%4];"
        : "=r"(r[0]), "=r"(r[1]), "=r"(r[2]), "=r"(r[3]) : "r"(addr));
}
__device__ __forceinline__ void mma_fp16(float* c, const uint32_t* a, uint32_t b0, uint32_t b1) {
    asm volatile("mma.sync.aligned.m16n8k16.row.col.f32.f16.f16.f32 "
        "{%0,%1,%2,%3}, {%4,%5,%6,%7}, {%8,%9}, {%0,%1,%2,%3};"
        : "+f"(c[0]), "+f"(c[1]), "+f"(c[2]), "+f"(c[3])
        : "r"(a[0]), "r"(a[1]), "r"(a[2]), "r"(a[3]), "r"(b0), "r"(b1));
}
__device__ __forceinline__ uint2 pack_half4(float x, float y, float z, float w) {
    __half2 lo = __floats2half2_rn(x, y);
    __half2 hi = __floats2half2_rn(z, w);
    uint2 v;
    v.x = *(uint32_t*)&lo;
    v.y = *(uint32_t*)&hi;
    return v;
}
// HW tanh (1 MUFU, sm_75+), independent of -use_fast_math
__device__ __forceinline__ float tanh_hw(float x) {
    float r;
    asm("tanh.approx.f32 %0, %1;" : "=f"(r) : "f"(x));
    return r;
}
// HW exp via ex2 (1 MUFU + 1 FMUL)
__device__ __forceinline__ float exp_hw(float x) {
    float r;
    float xl = x * 1.4426950408889634f;
    asm("ex2.approx.f32 %0, %1;" : "=f"(r) : "f"(xl));
    return r;
}

// ---------------------------------------------------------------------------
// Kernel 1: p = exp(W2 . tanh(f @ W1 + b1) + b2), fp16 MMA (round-7 config,
// best measured) with HW tanh/exp epilogue.
// ---------------------------------------------------------------------------
#define A1_STR 136
#define W1_STR 72
#define SM1_BYTES ((128*A1_STR + 128*W1_STR) * 2)

__global__ __launch_bounds__(256, 2) void k1_logits(
    const float* __restrict__ feats, const float* __restrict__ W1,
    const float* __restrict__ b1, const float* __restrict__ W2,
    const float* __restrict__ b2, int B)
{
    extern __shared__ __half sm1[];
    __half* aS = sm1;                  // [128 tok][136]
    __half* wS = sm1 + 128*A1_STR;     // [128 k][72]

    int tid = threadIdx.x;
    int tok0 = blockIdx.x * 128;
    int wid = tid >> 5, lane = tid & 31;

    #pragma unroll
    for (int i = 0; i < 16; i++) {
        int idx = tid + i*256;
        int row = idx >> 5, c4 = idx & 31;
        int tok = tok0 + row;
        float4 v = make_float4(0.f, 0.f, 0.f, 0.f);
        if (tok < B) v = ((const float4*)(feats + (size_t)tok*DDIM))[c4];
        *(uint2*)(aS + row*A1_STR + c4*4) = pack_half4(v.x, v.y, v.z, v.w);
    }
    #pragma unroll
    for (int i = 0; i < 8; i++) {
        int idx = tid + i*256;
        int row = idx >> 4, c4 = idx & 15;
        float4 v = ((const float4*)W1)[idx];
        *(uint2*)(wS + row*W1_STR + c4*4) = pack_half4(v.x, v.y, v.z, v.w);
    }
    __syncthreads();

    uint32_t aS_s = (uint32_t)__cvta_generic_to_shared(aS);
    uint32_t wS_s = (uint32_t)__cvta_generic_to_shared(wS);

    float acc[8][4];
    #pragma unroll
    for (int nt = 0; nt < 8; nt++)
        #pragma unroll
        for (int e = 0; e < 4; e++) acc[nt][e] = 0.f;

    #pragma unroll
    for (int ks = 0; ks < 8; ks++) {
        uint32_t a[4];
        ldsm_x4(a, aS_s + (uint32_t)(((wid*16 + (lane & 15)) * A1_STR
                          + ks*16 + ((lane >> 4) << 3)) * 2));
        #pragma unroll
        for (int np = 0; np < 4; np++) {
            uint32_t b[4];
            ldsm_x4_t(b, wS_s + (uint32_t)(((ks*16 + (lane & 15)) * W1_STR
                              + np*16 + ((lane >> 4) << 3)) * 2));
            mma_fp16(acc[np*2],     a, b[0], b[1]);
            mma_fp16(acc[np*2 + 1], a, b[2], b[3]);
        }
    }

    float s0 = 0.f, s1 = 0.f;
    #pragma unroll
    for (int nt = 0; nt < 8; nt++) {
        int j0 = nt*8 + (lane & 3)*2;
        float b1a = __ldg(b1 + j0), b1b = __ldg(b1 + j0 + 1);
        float w2a = __ldg(W2 + j0), w2b = __ldg(W2 + j0 + 1);
        s0 += tanh_hw(acc[nt][0] + b1a) * w2a + tanh_hw(acc[nt][1] + b1b) * w2b;
        s1 += tanh_hw(acc[nt][2] + b1a) * w2a + tanh_hw(acc[nt][3] + b1b) * w2b;
    }
    #pragma unroll
    for (int m = 1; m <= 2; m <<= 1) {
        s0 += __shfl_xor_sync(0xffffffffu, s0, m);
        s1 += __shfl_xor_sync(0xffffffffu, s1, m);
    }
    if ((lane & 3) == 0) {
        float bb2 = __ldg(b2);
        int r = lane >> 2;
        int tok = tok0 + wid*16 + r;
        if (tok < B)     g_p[tok]     = exp_hw(s0 + bb2);
        if (tok + 8 < B) g_p[tok + 8] = exp_hw(s1 + bb2);
    }
}

// ---------------------------------------------------------------------------
// Kernel 2: round-7 version verbatim (best measured). split-K fp16 MMA,
// KCHUNK=32, one 512-thread CTA per split covers all 256 l, register
// prefetch, double-buffered smem, 1 sync/chunk. warp = 32 l x 64 d.
// ---------------------------------------------------------------------------
#define MA_STR 40    // 32 k + 8 pad (halves)
#define G_STR  136   // 128 d + 8 pad (halves)
#define MA_HALVES (LTOT*MA_STR)   // 10240
#define G_HALVES  (KCHUNK*G_STR)  // 4352
#define SM2_BYTES ((2*MA_HALVES + 2*G_HALVES) * 2 + LTOT*8*4)

__global__ __launch_bounds__(512, 1) void k2_mma(
    const float* __restrict__ feats, const float* __restrict__ mask,
    int B, int chunksPerSplit)
{
    extern __shared__ char smraw[];
    __half* mA  = (__half*)smraw;                    // 2 x [256 l][40]
    __half* fS  = mA + 2*MA_HALVES;                  // 2 x [32 k][136]
    float*  zsm = (float*)(fS + 2*G_HALVES);         // [256][8]

    int tid  = threadIdx.x;
    int y    = blockIdx.x;
    int wid  = tid >> 5, lane = tid & 31;
    int wm   = wid & 7, wn = wid >> 3;

    float acc[2][8][4];
    #pragma unroll
    for (int mt = 0; mt < 2; mt++)
        #pragma unroll
        for (int nt = 0; nt < 8; nt++)
            #pragma unroll
            for (int e = 0; e < 4; e++) acc[mt][nt][e] = 0.f;
    float zacc[4] = {0.f, 0.f, 0.f, 0.f};

    uint32_t mA_s = (uint32_t)__cvta_generic_to_shared(mA);
    uint32_t fS_s = (uint32_t)__cvta_generic_to_shared(fS);

    int mrow = tid >> 3, mc4 = tid & 7;      // mask: l rows mrow+64i, k-col mc4*4

    float4 m4[4], f4[2], p4;
    int kb0 = y * chunksPerSplit * KCHUNK;

    // prologue: chunk 0 regs
    {
        int gk = kb0 + mc4*4;
        p4 = (gk < B) ? *((const float4*)(g_p + gk)) : make_float4(0.f,0.f,0.f,0.f);
        #pragma unroll
        for (int i = 0; i < 4; i++)
            m4[i] = (gk < B) ? *((const float4*)(mask + (size_t)(mrow + i*64)*B + gk))
                             : make_float4(0.f, 0.f, 0.f, 0.f);
        #pragma unroll
        for (int i = 0; i < 2; i++) {
            int idx = tid + i*512;
            int tok = kb0 + (idx >> 5);
            f4[i] = (tok < B) ? ((const float4*)(feats + (size_t)tok*DDIM))[idx & 31]
                              : make_float4(0.f, 0.f, 0.f, 0.f);
        }
    }

    for (int c = 0; c < chunksPerSplit; c++) {
        __half* mA_c = mA + (c & 1) * MA_HALVES;
        __half* fS_c = fS + (c & 1) * G_HALVES;

        // stage mp(c) = mask*p -> fp16; Z fused
        #pragma unroll
        for (int i = 0; i < 4; i++) {
            float4 v = m4[i];
            float mpx = v.x*p4.x, mpy = v.y*p4.y, mpz = v.z*p4.z, mpw = v.w*p4.w;
            zacc[i] += mpx + mpy + mpz + mpw;
            *(uint2*)(mA_c + (mrow + i*64)*MA_STR + mc4*4) = pack_half4(mpx, mpy, mpz, mpw);
        }
        // stage feats(c) fp32 regs -> fp16
        #pragma unroll
        for (int i = 0; i < 2; i++) {
            int idx = tid + i*512;
            *(uint2*)(fS_c + (idx >> 5)*G_STR + (idx & 31)*4)
                = pack_half4(f4[i].x, f4[i].y, f4[i].z, f4[i].w);
        }

        // prefetch chunk c+1 regs
        if (c + 1 < chunksPerSplit) {
            int kb2 = kb0 + (c + 1)*KCHUNK;
            int gk = kb2 + mc4*4;
            p4 = (gk < B) ? *((const float4*)(g_p + gk)) : make_float4(0.f,0.f,0.f,0.f);
            #pragma unroll
            for (int i = 0; i < 4; i++)
                m4[i] = (gk < B) ? *((const float4*)(mask + (size_t)(mrow + i*64)*B + gk))
                                 : make_float4(0.f, 0.f, 0.f, 0.f);
            #pragma unroll
            for (int i = 0; i < 2; i++) {
                int idx = tid + i*512;
                int tok = kb2 + (idx >> 5);
                f4[i] = (tok < B) ? ((const float4*)(feats + (size_t)tok*DDIM))[idx & 31]
                                  : make_float4(0.f, 0.f, 0.f, 0.f);
            }
        }
        __syncthreads();   // staged buffers visible; MMA(c-1) done

        // MMA over chunk c
        uint32_t mA_b = mA_s + (uint32_t)((c & 1) * MA_HALVES * 2);
        uint32_t fS_b = fS_s + (uint32_t)((c & 1) * G_HALVES * 2);
        #pragma unroll
        for (int ks = 0; ks < 2; ks++) {
            uint32_t a[2][4];
            #pragma unroll
            for (int mt = 0; mt < 2; mt++)
                ldsm_x4(a[mt], mA_b + (uint32_t)(((wm*32 + mt*16 + (lane & 15)) * MA_STR
                                 + ks*16 + ((lane >> 4) << 3)) * 2));
            #pragma unroll
            for (int np = 0; np < 4; np++) {
                uint32_t b[4];
                ldsm_x4_t(b, fS_b + (uint32_t)(((ks*16 + (lane & 15)) * G_STR
                                 + wn*64 + np*16 + ((lane >> 4) << 3)) * 2));
                #pragma unroll
                for (int mt = 0; mt < 2; mt++) {
                    mma_fp16(acc[mt][np*2],     a[mt], b[0], b[1]);
                    mma_fp16(acc[mt][np*2 + 1], a[mt], b[2], b[3]);
                }
            }
        }
    }

    // deterministic Z reduction
    __syncthreads();
    #pragma unroll
    for (int i = 0; i < 4; i++)
        zsm[(mrow + i*64)*8 + mc4] = zacc[i];
    __syncthreads();
    if (tid < LTOT) {
        float z = 0.f;
        #pragma unroll
        for (int j = 0; j < 8; j++) z += zsm[tid*8 + j];
        g_zpart[y*LTOT + tid] = z;
    }

    // write numerator partials
    #pragma unroll
    for (int mt = 0; mt < 2; mt++) {
        #pragma unroll
        for (int nt = 0; nt < 8; nt++) {
            int grow = wm*32 + mt*16 + (lane >> 2);
            int gcol = wn*64 + nt*8 + (lane & 3)*2;
            size_t b0 = ((size_t)y*LTOT + grow) * DDIM + gcol;
            size_t b1 = ((size_t)y*LTOT + grow + 8) * DDIM + gcol;
            *(float2*)(g_part + b0) = make_float2(acc[mt][nt][0], acc[mt][nt][1]);
            *(float2*)(g_part + b1) = make_float2(acc[mt][nt][2], acc[mt][nt][3]);
        }
    }
}

// ---------------------------------------------------------------------------
// Kernel 3: parallel reduce, FULL unroll -> all 37 loads in flight.
// ---------------------------------------------------------------------------
__global__ __launch_bounds__(512, 2) void k3_reduce(float* __restrict__ out)
{
    __shared__ float nsm[4][DDIM];
    __shared__ float zsm4[4];

    int l = blockIdx.x;
    int tid = threadIdx.x;
    int g = tid >> 7;
    int d = tid & 127;

    const float* pbase = g_part + ((size_t)(g*37)*LTOT + l) * DDIM + d;
    const float* zbase = g_zpart + (g*37)*LTOT + l;

    float n0 = 0.f, n1 = 0.f, z0 = 0.f, z1 = 0.f;
    #pragma unroll
    for (int yy = 0; yy < 37; yy += 2) {
        n0 += pbase[(size_t)yy * LTOT * DDIM];
        z0 += zbase[yy * LTOT];
    }
    #pragma unroll
    for (int yy = 1; yy < 37; yy += 2) {
        n1 += pbase[(size_t)yy * LTOT * DDIM];
        z1 += zbase[yy * LTOT];
    }
    nsm[g][d] = n0 + n1;
    if (d == 0) zsm4[g] = z0 + z1;
    __syncthreads();

    if (g == 0) {
        float n = nsm[0][d] + nsm[1][d] + nsm[2][d] + nsm[3][d];
        float zz = zsm4[0] + zsm4[1] + zsm4[2] + zsm4[3];
        out[l*DDIM + d] = (zz > 0.f) ? n / zz : 0.f;
    }
}

// ---------------------------------------------------------------------------
extern "C" void kernel_launch(void* const* d_in, const int* in_sizes, int n_in,
                              void* d_out, int out_size)
{
    const float* feats = (const float*)d_in[0];
    const float* mask  = (const float*)d_in[1];
    const float* W1    = (const float*)d_in[2];
    const float* b1    = (const float*)d_in[3];
    const float* W2    = (const float*)d_in[4];
    const float* b2    = (const float*)d_in[5];
    float* out = (float*)d_out;

    int B = in_sizes[0] / DDIM;           // 200000
    int totalChunks = (B + KCHUNK - 1) / KCHUNK;
    int cps = (totalChunks + SPLITK - 1) / SPLITK;

    cudaFuncSetAttribute(k1_logits, cudaFuncAttributeMaxDynamicSharedMemorySize, SM1_BYTES);
    cudaFuncSetAttribute(k2_mma,    cudaFuncAttributeMaxDynamicSharedMemorySize, SM2_BYTES);

    int g1 = (B + 127) / 128;
    k1_logits<<<g1, 256, SM1_BYTES>>>(feats, W1, b1, W2, b2, B);

    k2_mma<<<SPLITK, 512, SM2_BYTES>>>(feats, mask, B, cps);

    k3_reduce<<<LTOT, 512>>>(out);
}